// round 2
// baseline (speedup 1.0000x reference)
#include <cuda_runtime.h>

#define NN 100000
#define NE 1600000
#define FIN 256
#define FH 64
#define FC 16

typedef unsigned long long u64;

// ---- scratch (device globals; no runtime allocation allowed) ----
__device__ float g_dinv[NN];
__device__ int   g_hist[NN];            // in-degree histogram (no self-loop)
__device__ int   g_start[NN + 1];       // CSR row starts
__device__ int   g_cursor[NN];          // fill cursors
__device__ int   g_csr_src[NE];         // CSR column (source) indices
__device__ float g_h1[(size_t)NN * FH]; // x @ W1
__device__ float g_agg1[(size_t)NN * FH]; // relu(layer-1 output)
__device__ float g_h2[(size_t)NN * FC]; // agg1 @ W2
__device__ int   g_is64;

// ---------------------------------------------------------------
__global__ void k_detect(const void* ei) {
    const long long* p = (const long long*)ei;
    int ok = 1;
    for (int i = 0; i < 64; i++) {
        long long v = p[i];
        if (v < 0 || v >= NN) { ok = 0; break; }
    }
    g_is64 = ok;
}

__device__ __forceinline__ int load_idx(const void* ei, int which, int e) {
    if (g_is64) return (int)((const long long*)ei)[(size_t)which * NE + e];
    else        return ((const int*)ei)[(size_t)which * NE + e];
}

// ---------------------------------------------------------------
__global__ void k_zero_hist() {
    int i = blockIdx.x * blockDim.x + threadIdx.x;
    if (i < NN) g_hist[i] = 0;
}

__global__ void k_hist(const void* __restrict__ ei) {
    int e = blockIdx.x * blockDim.x + threadIdx.x;
    if (e < NE) atomicAdd(&g_hist[load_idx(ei, 1, e)], 1);
}

// one-block scan: start/cursor = exclusive scan(hist), dinv = rsqrt(hist+1)
__global__ void k_scan() {
    const int T = 1024;
    const int CHUNK = (NN + T - 1) / T;   // 98
    __shared__ int sm[T];
    int t = threadIdx.x;
    int base = t * CHUNK;

    int sum = 0;
    for (int i = 0; i < CHUNK; i++) {
        int idx = base + i;
        if (idx < NN) sum += g_hist[idx];
    }
    sm[t] = sum;
    __syncthreads();
    // Hillis-Steele inclusive scan
    for (int off = 1; off < T; off <<= 1) {
        int v = (t >= off) ? sm[t - off] : 0;
        __syncthreads();
        sm[t] += v;
        __syncthreads();
    }
    int run = (t > 0) ? sm[t - 1] : 0;
    for (int i = 0; i < CHUNK; i++) {
        int idx = base + i;
        if (idx < NN) {
            g_start[idx] = run;
            g_cursor[idx] = run;
            int h = g_hist[idx];
            run += h;
            g_dinv[idx] = rsqrtf((float)h + 1.0f);
        }
    }
    if (t == T - 1) g_start[NN] = NE;
}

__global__ void k_fill(const void* __restrict__ ei) {
    int e = blockIdx.x * blockDim.x + threadIdx.x;
    if (e >= NE) return;
    int s = load_idx(ei, 0, e);
    int d = load_idx(ei, 1, e);
    int pos = atomicAdd(&g_cursor[d], 1);
    g_csr_src[pos] = s;
}

// ---------------------------------------------------------------
__device__ __forceinline__ u64 fma2(u64 a, u64 b, u64 c) {
    u64 d;
    asm("fma.rn.f32x2 %0, %1, %2, %3;" : "=l"(d) : "l"(a), "l"(b), "l"(c));
    return d;
}
__device__ __forceinline__ u64 pack2(float x) {
    u64 d;
    asm("mov.b64 %0, {%1, %1};" : "=l"(d) : "f"(x));
    return d;
}

// GEMM1: h1[N,64] = x[N,256] @ W1[256,64]; 2 rows/thread, f32x2 packed FMA
__global__ __launch_bounds__(256, 1) void k_gemm1(const float* __restrict__ x,
                                                  const float* __restrict__ W1) {
    __shared__ float Ws[128 * FH];   // 32 KB K-tile
    int tid = threadIdx.x;
    int r0 = blockIdx.x * 512 + tid;
    int r1 = r0 + 256;
    bool v0 = r0 < NN, v1 = r1 < NN;

    u64 acc0[32], acc1[32];
#pragma unroll
    for (int j = 0; j < 32; j++) { acc0[j] = 0ULL; acc1[j] = 0ULL; }

    for (int kt = 0; kt < FIN; kt += 128) {
        __syncthreads();
        {
            const float4* wsrc = (const float4*)(W1 + (size_t)kt * FH);
            float4* wdst = (float4*)Ws;
#pragma unroll
            for (int i = 0; i < 8; i++)
                wdst[tid + i * 256] = wsrc[tid + i * 256];
        }
        __syncthreads();

        const float4* xr0 = (const float4*)(x + (size_t)r0 * FIN + kt);
        const float4* xr1 = (const float4*)(x + (size_t)r1 * FIN + kt);
        float4 z4 = make_float4(0.f, 0.f, 0.f, 0.f);
#pragma unroll 4
        for (int k4 = 0; k4 < 32; k4++) {
            float4 xa = v0 ? xr0[k4] : z4;
            float4 xb = v1 ? xr1[k4] : z4;
            float ax[4] = {xa.x, xa.y, xa.z, xa.w};
            float bx[4] = {xb.x, xb.y, xb.z, xb.w};
#pragma unroll
            for (int kk = 0; kk < 4; kk++) {
                u64 pa = pack2(ax[kk]);
                u64 pb = pack2(bx[kk]);
                const u64* w = (const u64*)&Ws[(k4 * 4 + kk) * FH];
#pragma unroll
                for (int j = 0; j < 32; j++) {
                    u64 wv = w[j];
                    acc0[j] = fma2(pa, wv, acc0[j]);
                    acc1[j] = fma2(pb, wv, acc1[j]);
                }
            }
        }
    }

    if (v0) {
        u64* dst = (u64*)&g_h1[(size_t)r0 * FH];
#pragma unroll
        for (int j = 0; j < 32; j++) dst[j] = acc0[j];
    }
    if (v1) {
        u64* dst = (u64*)&g_h1[(size_t)r1 * FH];
#pragma unroll
        for (int j = 0; j < 32; j++) dst[j] = acc1[j];
    }
}

// ---------------------------------------------------------------
// gather layer 1: one warp per dst node; agg1 = relu(b1 + sum + self)
__global__ __launch_bounds__(256) void k_gather1(const float* __restrict__ b1) {
    int node = blockIdx.x * 8 + (threadIdx.x >> 5);
    if (node >= NN) return;
    int lane = threadIdx.x & 31;

    float dd = g_dinv[node];
    float d2 = dd * dd;
    float2 self = *(const float2*)&g_h1[(size_t)node * FH + lane * 2];
    float2 acc;
    acc.x = self.x * d2;
    acc.y = self.y * d2;

    int beg = g_start[node];
    int end = g_start[node + 1];
    int s = (beg < end) ? g_csr_src[beg] : 0;
    for (int k = beg; k < end; k++) {
        int sn = (k + 1 < end) ? g_csr_src[k + 1] : 0;
        float n = g_dinv[s] * dd;
        float2 v = *(const float2*)&g_h1[(size_t)s * FH + lane * 2];
        acc.x += v.x * n;
        acc.y += v.y * n;
        s = sn;
    }
    float2 bb = *(const float2*)&b1[lane * 2];
    acc.x = fmaxf(acc.x + bb.x, 0.0f);
    acc.y = fmaxf(acc.y + bb.y, 0.0f);
    *(float2*)&g_agg1[(size_t)node * FH + lane * 2] = acc;
}

// ---------------------------------------------------------------
// GEMM2: h2 = agg1(already relu'd) @ W2[64,16]
__global__ __launch_bounds__(256) void k_gemm2(const float* __restrict__ W2) {
    __shared__ float Ws[FH * FC];
    for (int i = threadIdx.x; i < FH * FC; i += 256) Ws[i] = W2[i];
    __syncthreads();

    int row = blockIdx.x * 256 + threadIdx.x;
    if (row >= NN) return;

    float acc[FC];
#pragma unroll
    for (int j = 0; j < FC; j++) acc[j] = 0.0f;

    const float4* ar = (const float4*)&g_agg1[(size_t)row * FH];
#pragma unroll
    for (int k4 = 0; k4 < 16; k4++) {
        float4 h4 = ar[k4];
        float hv[4] = {h4.x, h4.y, h4.z, h4.w};
#pragma unroll
        for (int kk = 0; kk < 4; kk++) {
            const float4* wr = (const float4*)&Ws[(k4 * 4 + kk) * FC];
#pragma unroll
            for (int j4 = 0; j4 < 4; j4++) {
                float4 w = wr[j4];
                acc[j4 * 4 + 0] += hv[kk] * w.x;
                acc[j4 * 4 + 1] += hv[kk] * w.y;
                acc[j4 * 4 + 2] += hv[kk] * w.z;
                acc[j4 * 4 + 3] += hv[kk] * w.w;
            }
        }
    }
#pragma unroll
    for (int j = 0; j < FC; j += 4) {
        float4 h;
        h.x = acc[j]; h.y = acc[j + 1]; h.z = acc[j + 2]; h.w = acc[j + 3];
        *(float4*)&g_h2[(size_t)row * FC + j] = h;
    }
}

// gather layer 2: 16 lanes per dst node; writes out fully (covers poison)
__global__ __launch_bounds__(256) void k_gather2(const float* __restrict__ b2,
                                                 float* __restrict__ out) {
    int t = blockIdx.x * 256 + threadIdx.x;
    int node = t >> 4;
    if (node >= NN) return;
    int lane = t & 15;

    float dd = g_dinv[node];
    float d2 = dd * dd;
    float acc = g_h2[(size_t)node * FC + lane] * d2;

    int beg = g_start[node];
    int end = g_start[node + 1];
    int s = (beg < end) ? g_csr_src[beg] : 0;
    for (int k = beg; k < end; k++) {
        int sn = (k + 1 < end) ? g_csr_src[k + 1] : 0;
        float n = g_dinv[s] * dd;
        acc += g_h2[(size_t)s * FC + lane] * n;
        s = sn;
    }
    out[(size_t)node * FC + lane] = acc + b2[lane];
}

// ---------------------------------------------------------------
extern "C" void kernel_launch(void* const* d_in, const int* in_sizes, int n_in,
                              void* d_out, int out_size) {
    const float* x  = (const float*)d_in[0];
    const void*  ei = d_in[1];
    const float* W1 = (const float*)d_in[2];
    const float* b1 = (const float*)d_in[3];
    const float* W2 = (const float*)d_in[4];
    const float* b2 = (const float*)d_in[5];
    float* out = (float*)d_out;

    k_detect<<<1, 1>>>(ei);
    k_zero_hist<<<(NN + 255) / 256, 256>>>();
    k_hist<<<(NE + 255) / 256, 256>>>(ei);
    k_scan<<<1, 1024>>>();
    k_fill<<<(NE + 255) / 256, 256>>>(ei);
    k_gemm1<<<(NN + 511) / 512, 256>>>(x, W1);
    k_gather1<<<(NN + 7) / 8, 256>>>(b1);
    k_gemm2<<<(NN + 255) / 256, 256>>>(W2);
    {
        long long threads = (long long)NN * 16;
        k_gather2<<<(unsigned)((threads + 255) / 256), 256>>>(b2, out);
    }
}

// round 3
// speedup vs baseline: 1.7541x; 1.7541x over previous
#include <cuda_runtime.h>

#define NN 100000
#define NE 1600000
#define FIN 256
#define FH 64
#define FC 16
#define NB ((NN + 255) / 256)   // 391 scan blocks

typedef unsigned long long u64;

// ---- scratch (device globals; no runtime allocation allowed) ----
__device__ float g_dinv[NN];
__device__ int   g_hist[NN];
__device__ int   g_bsum[NB];
__device__ int   g_boff[NB];
__device__ int   g_start[NN + 1];
__device__ int   g_cursor[NN];
__device__ int   g_csr_src[NE];
__device__ float g_h1[(size_t)NN * FH];
__device__ float g_agg1[(size_t)NN * FH];
__device__ float g_h2[(size_t)NN * FC];
__device__ int   g_is64;

// ---------------------------------------------------------------
__global__ void k_detect(const void* ei) {
    const long long* p = (const long long*)ei;
    int ok = 1;
    for (int i = 0; i < 64; i++) {
        long long v = p[i];
        if (v < 0 || v >= NN) { ok = 0; break; }
    }
    g_is64 = ok;
}

__device__ __forceinline__ int load_idx(const void* ei, int which, int e) {
    if (g_is64) return (int)((const long long*)ei)[(size_t)which * NE + e];
    else        return ((const int*)ei)[(size_t)which * NE + e];
}

// ---------------------------------------------------------------
__global__ void k_zero_hist() {
    int i = blockIdx.x * blockDim.x + threadIdx.x;
    if (i < NN) g_hist[i] = 0;
}

__global__ void k_hist(const void* __restrict__ ei) {
    int e = blockIdx.x * blockDim.x + threadIdx.x;
    if (e < NE) atomicAdd(&g_hist[load_idx(ei, 1, e)], 1);
}

// ---- 3-phase parallel exclusive scan of g_hist -> g_start ----
__global__ void k_bsum() {
    __shared__ int sm[256];
    int i = blockIdx.x * 256 + threadIdx.x;
    sm[threadIdx.x] = (i < NN) ? g_hist[i] : 0;
    __syncthreads();
#pragma unroll
    for (int off = 128; off > 0; off >>= 1) {
        if (threadIdx.x < off) sm[threadIdx.x] += sm[threadIdx.x + off];
        __syncthreads();
    }
    if (threadIdx.x == 0) g_bsum[blockIdx.x] = sm[0];
}

__global__ void k_scan_top() {
    __shared__ int sm[512];
    int t = threadIdx.x;
    int v = (t < NB) ? g_bsum[t] : 0;
    sm[t] = v;
    __syncthreads();
#pragma unroll
    for (int off = 1; off < 512; off <<= 1) {
        int u = (t >= off) ? sm[t - off] : 0;
        __syncthreads();
        sm[t] += u;
        __syncthreads();
    }
    if (t < NB) g_boff[t] = sm[t] - v;   // exclusive
}

__global__ void k_starts() {
    __shared__ int sm[256];
    int i = blockIdx.x * 256 + threadIdx.x;
    int h = (i < NN) ? g_hist[i] : 0;
    sm[threadIdx.x] = h;
    __syncthreads();
#pragma unroll
    for (int off = 1; off < 256; off <<= 1) {
        int u = (threadIdx.x >= off) ? sm[threadIdx.x - off] : 0;
        __syncthreads();
        sm[threadIdx.x] += u;
        __syncthreads();
    }
    if (i < NN) {
        int excl = sm[threadIdx.x] - h + g_boff[blockIdx.x];
        g_start[i] = excl;
        g_cursor[i] = excl;
        g_dinv[i] = rsqrtf((float)h + 1.0f);
    }
    if (i == 0) g_start[NN] = NE;
}

__global__ void k_fill(const void* __restrict__ ei) {
    int e = blockIdx.x * blockDim.x + threadIdx.x;
    if (e >= NE) return;
    int s = load_idx(ei, 0, e);
    int d = load_idx(ei, 1, e);
    int pos = atomicAdd(&g_cursor[d], 1);
    g_csr_src[pos] = s;
}

// ---------------------------------------------------------------
__device__ __forceinline__ u64 fma2(u64 a, u64 b, u64 c) {
    u64 d;
    asm("fma.rn.f32x2 %0, %1, %2, %3;" : "=l"(d) : "l"(a), "l"(b), "l"(c));
    return d;
}
__device__ __forceinline__ u64 pack2(float x) {
    u64 d;
    asm("mov.b64 %0, {%1, %1};" : "=l"(d) : "f"(x));
    return d;
}

// GEMM1: h1[N,64] = x[N,256] @ W1[256,64]; 2 rows/thread, f32x2 packed FMA
__global__ __launch_bounds__(256, 1) void k_gemm1(const float* __restrict__ x,
                                                  const float* __restrict__ W1) {
    __shared__ float Ws[128 * FH];   // 32 KB K-tile
    int tid = threadIdx.x;
    int r0 = blockIdx.x * 512 + tid;
    int r1 = r0 + 256;
    bool v0 = r0 < NN, v1 = r1 < NN;

    u64 acc0[32], acc1[32];
#pragma unroll
    for (int j = 0; j < 32; j++) { acc0[j] = 0ULL; acc1[j] = 0ULL; }

    for (int kt = 0; kt < FIN; kt += 128) {
        __syncthreads();
        {
            const float4* wsrc = (const float4*)(W1 + (size_t)kt * FH);
            float4* wdst = (float4*)Ws;
#pragma unroll
            for (int i = 0; i < 8; i++)
                wdst[tid + i * 256] = wsrc[tid + i * 256];
        }
        __syncthreads();

        const float4* xr0 = (const float4*)(x + (size_t)r0 * FIN + kt);
        const float4* xr1 = (const float4*)(x + (size_t)r1 * FIN + kt);
        float4 z4 = make_float4(0.f, 0.f, 0.f, 0.f);
#pragma unroll 4
        for (int k4 = 0; k4 < 32; k4++) {
            float4 xa = v0 ? xr0[k4] : z4;
            float4 xb = v1 ? xr1[k4] : z4;
            float ax[4] = {xa.x, xa.y, xa.z, xa.w};
            float bx[4] = {xb.x, xb.y, xb.z, xb.w};
#pragma unroll
            for (int kk = 0; kk < 4; kk++) {
                u64 pa = pack2(ax[kk]);
                u64 pb = pack2(bx[kk]);
                const u64* w = (const u64*)&Ws[(k4 * 4 + kk) * FH];
#pragma unroll
                for (int j = 0; j < 32; j++) {
                    u64 wv = w[j];
                    acc0[j] = fma2(pa, wv, acc0[j]);
                    acc1[j] = fma2(pb, wv, acc1[j]);
                }
            }
        }
    }

    if (v0) {
        u64* dst = (u64*)&g_h1[(size_t)r0 * FH];
#pragma unroll
        for (int j = 0; j < 32; j++) dst[j] = acc0[j];
    }
    if (v1) {
        u64* dst = (u64*)&g_h1[(size_t)r1 * FH];
#pragma unroll
        for (int j = 0; j < 32; j++) dst[j] = acc1[j];
    }
}

// ---------------------------------------------------------------
// gather layer 1: one warp per dst node; agg1 = relu(b1 + sum + self)
__global__ __launch_bounds__(256) void k_gather1(const float* __restrict__ b1) {
    int node = blockIdx.x * 8 + (threadIdx.x >> 5);
    if (node >= NN) return;
    int lane = threadIdx.x & 31;

    float dd = g_dinv[node];
    float d2 = dd * dd;
    float2 self = *(const float2*)&g_h1[(size_t)node * FH + lane * 2];
    float2 acc;
    acc.x = self.x * d2;
    acc.y = self.y * d2;

    int beg = g_start[node];
    int end = g_start[node + 1];
    int s = (beg < end) ? g_csr_src[beg] : 0;
    for (int k = beg; k < end; k++) {
        int sn = (k + 1 < end) ? g_csr_src[k + 1] : 0;
        float n = g_dinv[s] * dd;
        float2 v = *(const float2*)&g_h1[(size_t)s * FH + lane * 2];
        acc.x += v.x * n;
        acc.y += v.y * n;
        s = sn;
    }
    float2 bb = *(const float2*)&b1[lane * 2];
    acc.x = fmaxf(acc.x + bb.x, 0.0f);
    acc.y = fmaxf(acc.y + bb.y, 0.0f);
    *(float2*)&g_agg1[(size_t)node * FH + lane * 2] = acc;
}

// ---------------------------------------------------------------
// GEMM2: h2 = agg1(already relu'd) @ W2[64,16]
__global__ __launch_bounds__(256) void k_gemm2(const float* __restrict__ W2) {
    __shared__ float Ws[FH * FC];
    for (int i = threadIdx.x; i < FH * FC; i += 256) Ws[i] = W2[i];
    __syncthreads();

    int row = blockIdx.x * 256 + threadIdx.x;
    if (row >= NN) return;

    float acc[FC];
#pragma unroll
    for (int j = 0; j < FC; j++) acc[j] = 0.0f;

    const float4* ar = (const float4*)&g_agg1[(size_t)row * FH];
#pragma unroll
    for (int k4 = 0; k4 < 16; k4++) {
        float4 h4 = ar[k4];
        float hv[4] = {h4.x, h4.y, h4.z, h4.w};
#pragma unroll
        for (int kk = 0; kk < 4; kk++) {
            const float4* wr = (const float4*)&Ws[(k4 * 4 + kk) * FC];
#pragma unroll
            for (int j4 = 0; j4 < 4; j4++) {
                float4 w = wr[j4];
                acc[j4 * 4 + 0] += hv[kk] * w.x;
                acc[j4 * 4 + 1] += hv[kk] * w.y;
                acc[j4 * 4 + 2] += hv[kk] * w.z;
                acc[j4 * 4 + 3] += hv[kk] * w.w;
            }
        }
    }
#pragma unroll
    for (int j = 0; j < FC; j += 4) {
        float4 h;
        h.x = acc[j]; h.y = acc[j + 1]; h.z = acc[j + 2]; h.w = acc[j + 3];
        *(float4*)&g_h2[(size_t)row * FC + j] = h;
    }
}

// gather layer 2: 16 lanes per dst node; writes out fully (covers poison)
__global__ __launch_bounds__(256) void k_gather2(const float* __restrict__ b2,
                                                 float* __restrict__ out) {
    int t = blockIdx.x * 256 + threadIdx.x;
    int node = t >> 4;
    if (node >= NN) return;
    int lane = t & 15;

    float dd = g_dinv[node];
    float d2 = dd * dd;
    float acc = g_h2[(size_t)node * FC + lane] * d2;

    int beg = g_start[node];
    int end = g_start[node + 1];
    int s = (beg < end) ? g_csr_src[beg] : 0;
    for (int k = beg; k < end; k++) {
        int sn = (k + 1 < end) ? g_csr_src[k + 1] : 0;
        float n = g_dinv[s] * dd;
        acc += g_h2[(size_t)s * FC + lane] * n;
        s = sn;
    }
    out[(size_t)node * FC + lane] = acc + b2[lane];
}

// ---------------------------------------------------------------
extern "C" void kernel_launch(void* const* d_in, const int* in_sizes, int n_in,
                              void* d_out, int out_size) {
    const float* x  = (const float*)d_in[0];
    const void*  ei = d_in[1];
    const float* W1 = (const float*)d_in[2];
    const float* b1 = (const float*)d_in[3];
    const float* W2 = (const float*)d_in[4];
    const float* b2 = (const float*)d_in[5];
    float* out = (float*)d_out;

    k_detect<<<1, 1>>>(ei);
    k_zero_hist<<<NB, 256>>>();
    k_hist<<<(NE + 255) / 256, 256>>>(ei);
    k_bsum<<<NB, 256>>>();
    k_scan_top<<<1, 512>>>();
    k_starts<<<NB, 256>>>();
    k_fill<<<(NE + 255) / 256, 256>>>(ei);
    k_gemm1<<<(NN + 511) / 512, 256>>>(x, W1);
    k_gather1<<<(NN + 7) / 8, 256>>>(b1);
    k_gemm2<<<(NN + 255) / 256, 256>>>(W2);
    {
        long long threads = (long long)NN * 16;
        k_gather2<<<(unsigned)((threads + 255) / 256), 256>>>(b2, out);
    }
}

// round 5
// speedup vs baseline: 2.5516x; 1.4547x over previous
#include <cuda_runtime.h>
#include <cstdint>

#define NN 100000
#define NE 1600000
#define FIN 256
#define FH 64
#define FC 16
#define NB ((NN + 255) / 256)   // 391 scan blocks

typedef unsigned long long u64;

// ---- scratch (device globals; no runtime allocation allowed) ----
__device__ float g_dinv[NN];
__device__ int   g_hist[NN];
__device__ int   g_bsum[NB];
__device__ int   g_boff[NB];
__device__ int   g_start[NN + 1];
__device__ int   g_cursor[NN];
__device__ int   g_csr_src[NE];
__device__ float g_h1[(size_t)NN * FH];
__device__ float g_agg1[(size_t)NN * FH];
__device__ float g_h2[(size_t)NN * FC];
__device__ int   g_is64;

// ---------------------------------------------------------------
__global__ void k_detect(const void* ei) {
    const long long* p = (const long long*)ei;
    int ok = 1;
    for (int i = 0; i < 64; i++) {
        long long v = p[i];
        if (v < 0 || v >= NN) { ok = 0; break; }
    }
    g_is64 = ok;
}

__device__ __forceinline__ int load_idx(const void* ei, int which, int e) {
    if (g_is64) return (int)((const long long*)ei)[(size_t)which * NE + e];
    else        return ((const int*)ei)[(size_t)which * NE + e];
}

// ---------------------------------------------------------------
__global__ void k_zero_hist() {
    int i = blockIdx.x * blockDim.x + threadIdx.x;
    if (i < NN) g_hist[i] = 0;
}

__global__ void k_hist(const void* __restrict__ ei) {
    int e = blockIdx.x * blockDim.x + threadIdx.x;
    if (e < NE) atomicAdd(&g_hist[load_idx(ei, 1, e)], 1);
}

// ===================================================================
// GEMM1 via mma.sync tf32 (portable tensor path, sm_80+)
// Block: 256 threads (8 warps), 256 rows x 64 cols, K=256 in 4 tiles of 64.
// Warp w: rows [w*32, w*32+32) = 2 m-tiles of 16; 8 n-tiles of 8.
// ===================================================================
#define G1_THREADS 256
#define G1_ROWS 256
#define A_STRIDE 68            // floats; (4r+c)%32 distinct -> conflict-free A frags
#define B_STRIDE 260           // floats; (4n+k)%32 distinct -> conflict-free B frags
#define SM_AS_BYTES (G1_ROWS * A_STRIDE * 4)          // 69632
#define SM_BS_OFF   SM_AS_BYTES
#define SM1_TOTAL   (SM_AS_BYTES + FH * B_STRIDE * 4) // +66560 = 136192

__device__ __forceinline__ uint32_t cvt_tf32(float f) {
    uint32_t u;
    asm("cvt.rna.tf32.f32 %0, %1;" : "=r"(u) : "f"(f));
    return u;
}

__device__ __forceinline__ void mma_tf32(float* c, const uint32_t* a,
                                         uint32_t b0, uint32_t b1) {
    asm volatile(
        "mma.sync.aligned.m16n8k8.row.col.f32.tf32.tf32.f32 "
        "{%0,%1,%2,%3}, {%4,%5,%6,%7}, {%8,%9}, {%0,%1,%2,%3};"
        : "+f"(c[0]), "+f"(c[1]), "+f"(c[2]), "+f"(c[3])
        : "r"(a[0]), "r"(a[1]), "r"(a[2]), "r"(a[3]), "r"(b0), "r"(b1));
}

__global__ void __launch_bounds__(G1_THREADS, 1) k_gemm1(const float* __restrict__ x,
                                                         const float* __restrict__ W1) {
    extern __shared__ uint32_t smem[];
    uint32_t* As = smem;                          // [256][A_STRIDE]
    uint32_t* Bs = smem + SM_AS_BYTES / 4;        // [64][B_STRIDE]  (W1 transposed)

    int tid = threadIdx.x;
    int w = tid >> 5;
    int lane = tid & 31;
    int lr = lane >> 2;        // 0..7
    int lc = lane & 3;         // 0..3
    int base = blockIdx.x * G1_ROWS;

    // stage B = W1^T once (tf32-rounded)
    for (int idx = tid; idx < FIN * FH; idx += G1_THREADS) {
        int k = idx >> 6;
        int n = idx & 63;
        Bs[n * B_STRIDE + k] = cvt_tf32(W1[idx]);
    }

    float c[2][8][4];
#pragma unroll
    for (int m = 0; m < 2; m++)
#pragma unroll
        for (int nt = 0; nt < 8; nt++)
#pragma unroll
            for (int i = 0; i < 4; i++) c[m][nt][i] = 0.0f;

    for (int kt = 0; kt < 4; kt++) {
        __syncthreads();
        // stage A tile: rows [base, base+256), k in [kt*64, kt*64+64)
#pragma unroll
        for (int it = 0; it < 16; it++) {
            int idx = tid + it * G1_THREADS;
            int row = idx >> 4;
            int c4 = idx & 15;
            float4 v = make_float4(0.f, 0.f, 0.f, 0.f);
            int gr = base + row;
            if (gr < NN) v = *(const float4*)(x + (size_t)gr * FIN + kt * 64 + c4 * 4);
            uint4 t;
            t.x = cvt_tf32(v.x); t.y = cvt_tf32(v.y); t.z = cvt_tf32(v.z); t.w = cvt_tf32(v.w);
            *(uint4*)&As[row * A_STRIDE + c4 * 4] = t;
        }
        __syncthreads();

        int r0 = w * 32 + lr;
#pragma unroll
        for (int ks = 0; ks < 8; ks++) {
            int kk = ks * 8 + lc;
            uint32_t a[2][4];
            a[0][0] = As[(r0)      * A_STRIDE + kk];
            a[0][1] = As[(r0 + 8)  * A_STRIDE + kk];
            a[0][2] = As[(r0)      * A_STRIDE + kk + 4];
            a[0][3] = As[(r0 + 8)  * A_STRIDE + kk + 4];
            a[1][0] = As[(r0 + 16) * A_STRIDE + kk];
            a[1][1] = As[(r0 + 24) * A_STRIDE + kk];
            a[1][2] = As[(r0 + 16) * A_STRIDE + kk + 4];
            a[1][3] = As[(r0 + 24) * A_STRIDE + kk + 4];
            int kg = kt * 64 + ks * 8 + lc;
#pragma unroll
            for (int nt = 0; nt < 8; nt++) {
                uint32_t b0 = Bs[(nt * 8 + lr) * B_STRIDE + kg];
                uint32_t b1 = Bs[(nt * 8 + lr) * B_STRIDE + kg + 4];
                mma_tf32(c[0][nt], a[0], b0, b1);
                mma_tf32(c[1][nt], a[1], b0, b1);
            }
        }
    }

    // epilogue: c0,c1 -> (row, 2lc), c2,c3 -> (row+8, 2lc); float2 stores
#pragma unroll
    for (int m = 0; m < 2; m++) {
        int rowa = base + w * 32 + m * 16 + lr;
        int rowb = rowa + 8;
#pragma unroll
        for (int nt = 0; nt < 8; nt++) {
            int col = nt * 8 + 2 * lc;
            if (rowa < NN)
                *(float2*)&g_h1[(size_t)rowa * FH + col] = make_float2(c[m][nt][0], c[m][nt][1]);
            if (rowb < NN)
                *(float2*)&g_h1[(size_t)rowb * FH + col] = make_float2(c[m][nt][2], c[m][nt][3]);
        }
    }
}

// ---- 3-phase parallel exclusive scan of g_hist -> g_start ----
__global__ void k_bsum() {
    __shared__ int sm[256];
    int i = blockIdx.x * 256 + threadIdx.x;
    sm[threadIdx.x] = (i < NN) ? g_hist[i] : 0;
    __syncthreads();
#pragma unroll
    for (int off = 128; off > 0; off >>= 1) {
        if (threadIdx.x < off) sm[threadIdx.x] += sm[threadIdx.x + off];
        __syncthreads();
    }
    if (threadIdx.x == 0) g_bsum[blockIdx.x] = sm[0];
}

__global__ void k_scan_top() {
    __shared__ int sm[512];
    int t = threadIdx.x;
    int v = (t < NB) ? g_bsum[t] : 0;
    sm[t] = v;
    __syncthreads();
#pragma unroll
    for (int off = 1; off < 512; off <<= 1) {
        int u = (t >= off) ? sm[t - off] : 0;
        __syncthreads();
        sm[t] += u;
        __syncthreads();
    }
    if (t < NB) g_boff[t] = sm[t] - v;   // exclusive
}

__global__ void k_starts() {
    __shared__ int sm[256];
    int i = blockIdx.x * 256 + threadIdx.x;
    int h = (i < NN) ? g_hist[i] : 0;
    sm[threadIdx.x] = h;
    __syncthreads();
#pragma unroll
    for (int off = 1; off < 256; off <<= 1) {
        int u = (threadIdx.x >= off) ? sm[threadIdx.x - off] : 0;
        __syncthreads();
        sm[threadIdx.x] += u;
        __syncthreads();
    }
    if (i < NN) {
        int excl = sm[threadIdx.x] - h + g_boff[blockIdx.x];
        g_start[i] = excl;
        g_cursor[i] = excl;
        g_dinv[i] = rsqrtf((float)h + 1.0f);
    }
    if (i == 0) g_start[NN] = NE;
}

__global__ void k_fill(const void* __restrict__ ei) {
    int e = blockIdx.x * blockDim.x + threadIdx.x;
    if (e >= NE) return;
    int s = load_idx(ei, 0, e);
    int d = load_idx(ei, 1, e);
    int pos = atomicAdd(&g_cursor[d], 1);
    g_csr_src[pos] = s;
}

// ---------------------------------------------------------------
// gather layer 1: one warp per dst node; agg1 = relu(b1 + sum + self)
__global__ __launch_bounds__(256) void k_gather1(const float* __restrict__ b1) {
    int node = blockIdx.x * 8 + (threadIdx.x >> 5);
    if (node >= NN) return;
    int lane = threadIdx.x & 31;

    float dd = g_dinv[node];
    float d2 = dd * dd;
    float2 self = *(const float2*)&g_h1[(size_t)node * FH + lane * 2];
    float2 acc;
    acc.x = self.x * d2;
    acc.y = self.y * d2;

    int beg = g_start[node];
    int end = g_start[node + 1];
    int s = (beg < end) ? g_csr_src[beg] : 0;
    for (int k = beg; k < end; k++) {
        int sn = (k + 1 < end) ? g_csr_src[k + 1] : 0;
        float n = g_dinv[s] * dd;
        float2 v = *(const float2*)&g_h1[(size_t)s * FH + lane * 2];
        acc.x += v.x * n;
        acc.y += v.y * n;
        s = sn;
    }
    float2 bb = *(const float2*)&b1[lane * 2];
    acc.x = fmaxf(acc.x + bb.x, 0.0f);
    acc.y = fmaxf(acc.y + bb.y, 0.0f);
    *(float2*)&g_agg1[(size_t)node * FH + lane * 2] = acc;
}

// ---------------------------------------------------------------
// GEMM2: h2 = agg1(already relu'd) @ W2[64,16]
__global__ __launch_bounds__(256) void k_gemm2(const float* __restrict__ W2) {
    __shared__ float Ws[FH * FC];
    for (int i = threadIdx.x; i < FH * FC; i += 256) Ws[i] = W2[i];
    __syncthreads();

    int row = blockIdx.x * 256 + threadIdx.x;
    if (row >= NN) return;

    float acc[FC];
#pragma unroll
    for (int j = 0; j < FC; j++) acc[j] = 0.0f;

    const float4* ar = (const float4*)&g_agg1[(size_t)row * FH];
#pragma unroll
    for (int k4 = 0; k4 < 16; k4++) {
        float4 h4 = ar[k4];
        float hv[4] = {h4.x, h4.y, h4.z, h4.w};
#pragma unroll
        for (int kk = 0; kk < 4; kk++) {
            const float4* wr = (const float4*)&Ws[(k4 * 4 + kk) * FC];
#pragma unroll
            for (int j4 = 0; j4 < 4; j4++) {
                float4 w = wr[j4];
                acc[j4 * 4 + 0] += hv[kk] * w.x;
                acc[j4 * 4 + 1] += hv[kk] * w.y;
                acc[j4 * 4 + 2] += hv[kk] * w.z;
                acc[j4 * 4 + 3] += hv[kk] * w.w;
            }
        }
    }
#pragma unroll
    for (int j = 0; j < FC; j += 4) {
        float4 h;
        h.x = acc[j]; h.y = acc[j + 1]; h.z = acc[j + 2]; h.w = acc[j + 3];
        *(float4*)&g_h2[(size_t)row * FC + j] = h;
    }
}

// gather layer 2: 16 lanes per dst node; writes out fully (covers poison)
__global__ __launch_bounds__(256) void k_gather2(const float* __restrict__ b2,
                                                 float* __restrict__ out) {
    int t = blockIdx.x * 256 + threadIdx.x;
    int node = t >> 4;
    if (node >= NN) return;
    int lane = t & 15;

    float dd = g_dinv[node];
    float d2 = dd * dd;
    float acc = g_h2[(size_t)node * FC + lane] * d2;

    int beg = g_start[node];
    int end = g_start[node + 1];
    int s = (beg < end) ? g_csr_src[beg] : 0;
    for (int k = beg; k < end; k++) {
        int sn = (k + 1 < end) ? g_csr_src[k + 1] : 0;
        float n = g_dinv[s] * dd;
        acc += g_h2[(size_t)s * FC + lane] * n;
        s = sn;
    }
    out[(size_t)node * FC + lane] = acc + b2[lane];
}

// ---------------------------------------------------------------
extern "C" void kernel_launch(void* const* d_in, const int* in_sizes, int n_in,
                              void* d_out, int out_size) {
    const float* x  = (const float*)d_in[0];
    const void*  ei = d_in[1];
    const float* W1 = (const float*)d_in[2];
    const float* b1 = (const float*)d_in[3];
    const float* W2 = (const float*)d_in[4];
    const float* b2 = (const float*)d_in[5];
    float* out = (float*)d_out;

    cudaFuncSetAttribute(k_gemm1, cudaFuncAttributeMaxDynamicSharedMemorySize, SM1_TOTAL);

    k_detect<<<1, 1>>>(ei);
    k_zero_hist<<<NB, 256>>>();
    k_hist<<<(NE + 255) / 256, 256>>>(ei);
    k_gemm1<<<(NN + G1_ROWS - 1) / G1_ROWS, G1_THREADS, SM1_TOTAL>>>(x, W1);  // 4th -> profiled
    k_bsum<<<NB, 256>>>();
    k_scan_top<<<1, 512>>>();
    k_starts<<<NB, 256>>>();
    k_fill<<<(NE + 255) / 256, 256>>>(ei);
    k_gather1<<<(NN + 7) / 8, 256>>>(b1);
    k_gemm2<<<(NN + 255) / 256, 256>>>(W2);
    {
        long long threads = (long long)NN * 16;
        k_gather2<<<(unsigned)((threads + 255) / 256), 256>>>(b2, out);
    }
}

// round 6
// speedup vs baseline: 2.6846x; 1.0521x over previous
#include <cuda_runtime.h>
#include <cstdint>

#define NN 100000
#define NE 1600000
#define FIN 256
#define FH 64
#define FC 16
#define NB ((NN + 255) / 256)   // 391 blocks over nodes

typedef unsigned long long u64;

// ---- scratch (device globals; no runtime allocation allowed) ----
__device__ float g_dinv[NN];
__device__ int   g_hist[NN];
__device__ int   g_start[NN];
__device__ int   g_cursor[NN];
__device__ int   g_csr_src[NE];
__device__ int   g_alloc;
__device__ float g_h1[(size_t)NN * FH];
__device__ float g_agg1[(size_t)NN * FH];
__device__ float g_h2[(size_t)NN * FC];
__device__ int   g_is64;

// ---------------------------------------------------------------
__global__ void k_detect(const void* ei) {
    const long long* p = (const long long*)ei;
    int ok = 1;
    for (int i = 0; i < 64; i++) {
        long long v = p[i];
        if (v < 0 || v >= NN) { ok = 0; break; }
    }
    g_is64 = ok;
    g_alloc = 0;
}

__device__ __forceinline__ int load_idx(const void* ei, int which, int e) {
    if (g_is64) return (int)((const long long*)ei)[(size_t)which * NE + e];
    else        return ((const int*)ei)[(size_t)which * NE + e];
}

// ---------------------------------------------------------------
__global__ void k_zero_hist() {
    int i = blockIdx.x * blockDim.x + threadIdx.x;
    if (i < NN) g_hist[i] = 0;
}

__global__ void k_hist(const void* __restrict__ ei) {
    int e = blockIdx.x * blockDim.x + threadIdx.x;
    if (e < NE) atomicAdd(&g_hist[load_idx(ei, 1, e)], 1);
}

// ===================================================================
// GEMM1 via mma.sync tf32, cp.async double-buffered pipeline.
// Block: 256 threads (8 warps), 128 rows, K=256 in 8 tiles of 32.
// Warp w: mg=w&3 selects 32 rows (2 m-tiles), ng=w>>2 selects 4 n-tiles.
// ===================================================================
#define G1_THREADS 256
#define G1_ROWS 128
#define KT 32
#define NKT (FIN / KT)          // 8
#define A_STRIDE 36             // u32; (4r+c)%32 distinct -> conflict-free frags
#define B_STRIDE 260
#define A_BUF_U32 (G1_ROWS * A_STRIDE)          // 4608
#define SM1_TOTAL ((2 * A_BUF_U32 + FH * B_STRIDE) * 4)   // 103424 B

__device__ __forceinline__ uint32_t smem_u32(const void* p) {
    uint32_t a;
    asm("{ .reg .u64 t; cvta.to.shared.u64 t, %1; cvt.u32.u64 %0, t; }" : "=r"(a) : "l"(p));
    return a;
}
__device__ __forceinline__ uint32_t cvt_tf32(uint32_t f) {
    uint32_t u;
    asm("cvt.rna.tf32.f32 %0, %1;" : "=r"(u) : "r"(f));
    return u;
}
__device__ __forceinline__ uint32_t cvt_tf32f(float f) {
    uint32_t u;
    asm("cvt.rna.tf32.f32 %0, %1;" : "=r"(u) : "f"(f));
    return u;
}
__device__ __forceinline__ void mma_tf32(float* c, const uint32_t* a,
                                         uint32_t b0, uint32_t b1) {
    asm volatile(
        "mma.sync.aligned.m16n8k8.row.col.f32.tf32.tf32.f32 "
        "{%0,%1,%2,%3}, {%4,%5,%6,%7}, {%8,%9}, {%0,%1,%2,%3};"
        : "+f"(c[0]), "+f"(c[1]), "+f"(c[2]), "+f"(c[3])
        : "r"(a[0]), "r"(a[1]), "r"(a[2]), "r"(a[3]), "r"(b0), "r"(b1));
}

__device__ __forceinline__ void issue_tile(uint32_t dst_base, const float* __restrict__ x,
                                           int base, int kt, int tid) {
#pragma unroll
    for (int it = 0; it < 4; it++) {
        int idx = tid + it * G1_THREADS;
        int row = idx >> 3;
        int c4 = idx & 7;
        int gr = base + row;
        int ok = (gr < NN) ? 16 : 0;
        int gs = (gr < NN) ? gr : (NN - 1);
        const float* src = x + (size_t)gs * FIN + kt * KT + c4 * 4;
        uint32_t dst = dst_base + row * (A_STRIDE * 4) + c4 * 16;
        asm volatile("cp.async.ca.shared.global [%0], [%1], 16, %2;"
                     :: "r"(dst), "l"(src), "r"(ok) : "memory");
    }
    asm volatile("cp.async.commit_group;" ::: "memory");
}

__global__ void __launch_bounds__(G1_THREADS, 2) k_gemm1(const float* __restrict__ x,
                                                         const float* __restrict__ W1) {
    extern __shared__ uint32_t smem[];
    uint32_t* As = smem;                     // [2][128][A_STRIDE]
    uint32_t* Bs = smem + 2 * A_BUF_U32;     // [64][B_STRIDE] (W1^T, tf32)
    uint32_t asu = smem_u32(As);

    int tid = threadIdx.x;
    int w = tid >> 5;
    int lane = tid & 31;
    int lr = lane >> 2;
    int lc = lane & 3;
    int mg = w & 3;            // m-group: rows mg*32..mg*32+31
    int ng = w >> 2;           // n-group: n-tiles ng*4..ng*4+3
    int base = blockIdx.x * G1_ROWS;

    issue_tile(asu, x, base, 0, tid);

    // stage B = W1^T (tf32), vectorized read
    {
        const float4* w4 = (const float4*)W1;
#pragma unroll
        for (int it = 0; it < 16; it++) {
            int idx = tid + it * G1_THREADS;      // 4096 float4s
            int k = idx >> 4;
            int n4 = idx & 15;
            float4 v = w4[idx];
            Bs[(n4 * 4 + 0) * B_STRIDE + k] = cvt_tf32f(v.x);
            Bs[(n4 * 4 + 1) * B_STRIDE + k] = cvt_tf32f(v.y);
            Bs[(n4 * 4 + 2) * B_STRIDE + k] = cvt_tf32f(v.z);
            Bs[(n4 * 4 + 3) * B_STRIDE + k] = cvt_tf32f(v.w);
        }
    }

    float c[2][4][4];
#pragma unroll
    for (int m = 0; m < 2; m++)
#pragma unroll
        for (int j = 0; j < 4; j++)
#pragma unroll
            for (int i = 0; i < 4; i++) c[m][j][i] = 0.0f;

    int ar = mg * 32 + lr;

#pragma unroll
    for (int kt = 0; kt < NKT; kt++) {
        if (kt + 1 < NKT)
            issue_tile(asu + ((kt + 1) & 1) * (A_BUF_U32 * 4), x, base, kt + 1, tid);

        if (kt + 1 < NKT) asm volatile("cp.async.wait_group 1;" ::: "memory");
        else              asm volatile("cp.async.wait_group 0;" ::: "memory");
        __syncthreads();

        const uint32_t* A = As + (kt & 1) * A_BUF_U32;
#pragma unroll
        for (int ks = 0; ks < 4; ks++) {
            int kk = ks * 8 + lc;
            uint32_t a[8];
            a[0] = cvt_tf32(A[(ar)      * A_STRIDE + kk]);
            a[1] = cvt_tf32(A[(ar + 8)  * A_STRIDE + kk]);
            a[2] = cvt_tf32(A[(ar)      * A_STRIDE + kk + 4]);
            a[3] = cvt_tf32(A[(ar + 8)  * A_STRIDE + kk + 4]);
            a[4] = cvt_tf32(A[(ar + 16) * A_STRIDE + kk]);
            a[5] = cvt_tf32(A[(ar + 24) * A_STRIDE + kk]);
            a[6] = cvt_tf32(A[(ar + 16) * A_STRIDE + kk + 4]);
            a[7] = cvt_tf32(A[(ar + 24) * A_STRIDE + kk + 4]);
            int kg = kt * KT + ks * 8 + lc;
#pragma unroll
            for (int j = 0; j < 4; j++) {
                int brow = (ng * 4 + j) * 8 + lr;
                uint32_t b0 = Bs[brow * B_STRIDE + kg];
                uint32_t b1 = Bs[brow * B_STRIDE + kg + 4];
                mma_tf32(c[0][j], a, b0, b1);
                mma_tf32(c[1][j], a + 4, b0, b1);
            }
        }
        __syncthreads();
    }

    // epilogue
#pragma unroll
    for (int m = 0; m < 2; m++) {
        int rowa = base + mg * 32 + m * 16 + lr;
        int rowb = rowa + 8;
#pragma unroll
        for (int j = 0; j < 4; j++) {
            int col = (ng * 4 + j) * 8 + 2 * lc;
            if (rowa < NN)
                *(float2*)&g_h1[(size_t)rowa * FH + col] = make_float2(c[m][j][0], c[m][j][1]);
            if (rowb < NN)
                *(float2*)&g_h1[(size_t)rowb * FH + col] = make_float2(c[m][j][2], c[m][j][3]);
        }
    }
}

// ---- single-kernel CSR offset allocation (atomic block base) ----
__global__ void k_starts() {
    __shared__ int sm[256];
    __shared__ int sbase;
    int t = threadIdx.x;
    int i = blockIdx.x * 256 + t;
    int h = (i < NN) ? g_hist[i] : 0;
    sm[t] = h;
    __syncthreads();
#pragma unroll
    for (int off = 1; off < 256; off <<= 1) {
        int u = (t >= off) ? sm[t - off] : 0;
        __syncthreads();
        sm[t] += u;
        __syncthreads();
    }
    if (t == 255) sbase = atomicAdd(&g_alloc, sm[255]);
    __syncthreads();
    if (i < NN) {
        int excl = sbase + sm[t] - h;
        g_start[i] = excl;
        g_cursor[i] = excl;
        g_dinv[i] = rsqrtf((float)h + 1.0f);
    }
}

__global__ void k_fill(const void* __restrict__ ei) {
    int e = blockIdx.x * blockDim.x + threadIdx.x;
    if (e >= NE) return;
    int s = load_idx(ei, 0, e);
    int d = load_idx(ei, 1, e);
    int pos = atomicAdd(&g_cursor[d], 1);
    g_csr_src[pos] = s;
}

// ---------------------------------------------------------------
// gather layer 1: one warp per dst node; agg1 = relu(b1 + sum + self)
__global__ __launch_bounds__(256) void k_gather1(const float* __restrict__ b1) {
    int node = blockIdx.x * 8 + (threadIdx.x >> 5);
    if (node >= NN) return;
    int lane = threadIdx.x & 31;

    float dd = g_dinv[node];
    float d2 = dd * dd;
    float2 self = *(const float2*)&g_h1[(size_t)node * FH + lane * 2];
    float2 acc;
    acc.x = self.x * d2;
    acc.y = self.y * d2;

    int beg = g_start[node];
    int end = beg + g_hist[node];
    int s = (beg < end) ? g_csr_src[beg] : 0;
    for (int k = beg; k < end; k++) {
        int sn = (k + 1 < end) ? g_csr_src[k + 1] : 0;
        float n = g_dinv[s] * dd;
        float2 v = *(const float2*)&g_h1[(size_t)s * FH + lane * 2];
        acc.x += v.x * n;
        acc.y += v.y * n;
        s = sn;
    }
    float2 bb = *(const float2*)&b1[lane * 2];
    acc.x = fmaxf(acc.x + bb.x, 0.0f);
    acc.y = fmaxf(acc.y + bb.y, 0.0f);
    *(float2*)&g_agg1[(size_t)node * FH + lane * 2] = acc;
}

// ---------------------------------------------------------------
// GEMM2: h2 = agg1(already relu'd) @ W2[64,16]
__global__ __launch_bounds__(256) void k_gemm2(const float* __restrict__ W2) {
    __shared__ float Ws[FH * FC];
    for (int i = threadIdx.x; i < FH * FC; i += 256) Ws[i] = W2[i];
    __syncthreads();

    int row = blockIdx.x * 256 + threadIdx.x;
    if (row >= NN) return;

    float acc[FC];
#pragma unroll
    for (int j = 0; j < FC; j++) acc[j] = 0.0f;

    const float4* ar = (const float4*)&g_agg1[(size_t)row * FH];
#pragma unroll
    for (int k4 = 0; k4 < 16; k4++) {
        float4 h4 = ar[k4];
        float hv[4] = {h4.x, h4.y, h4.z, h4.w};
#pragma unroll
        for (int kk = 0; kk < 4; kk++) {
            const float4* wr = (const float4*)&Ws[(k4 * 4 + kk) * FC];
#pragma unroll
            for (int j4 = 0; j4 < 4; j4++) {
                float4 w = wr[j4];
                acc[j4 * 4 + 0] += hv[kk] * w.x;
                acc[j4 * 4 + 1] += hv[kk] * w.y;
                acc[j4 * 4 + 2] += hv[kk] * w.z;
                acc[j4 * 4 + 3] += hv[kk] * w.w;
            }
        }
    }
#pragma unroll
    for (int j = 0; j < FC; j += 4) {
        float4 h;
        h.x = acc[j]; h.y = acc[j + 1]; h.z = acc[j + 2]; h.w = acc[j + 3];
        *(float4*)&g_h2[(size_t)row * FC + j] = h;
    }
}

// gather layer 2: 16 lanes per dst node; writes out fully (covers poison)
__global__ __launch_bounds__(256) void k_gather2(const float* __restrict__ b2,
                                                 float* __restrict__ out) {
    int t = blockIdx.x * 256 + threadIdx.x;
    int node = t >> 4;
    if (node >= NN) return;
    int lane = t & 15;

    float dd = g_dinv[node];
    float d2 = dd * dd;
    float acc = g_h2[(size_t)node * FC + lane] * d2;

    int beg = g_start[node];
    int end = beg + g_hist[node];
    int s = (beg < end) ? g_csr_src[beg] : 0;
    for (int k = beg; k < end; k++) {
        int sn = (k + 1 < end) ? g_csr_src[k + 1] : 0;
        float n = g_dinv[s] * dd;
        acc += g_h2[(size_t)s * FC + lane] * n;
        s = sn;
    }
    out[(size_t)node * FC + lane] = acc + b2[lane];
}

// ---------------------------------------------------------------
extern "C" void kernel_launch(void* const* d_in, const int* in_sizes, int n_in,
                              void* d_out, int out_size) {
    const float* x  = (const float*)d_in[0];
    const void*  ei = d_in[1];
    const float* W1 = (const float*)d_in[2];
    const float* b1 = (const float*)d_in[3];
    const float* W2 = (const float*)d_in[4];
    const float* b2 = (const float*)d_in[5];
    float* out = (float*)d_out;

    cudaFuncSetAttribute(k_gemm1, cudaFuncAttributeMaxDynamicSharedMemorySize, SM1_TOTAL);

    k_detect<<<1, 1>>>(ei);
    k_zero_hist<<<NB, 256>>>();
    k_hist<<<(NE + 255) / 256, 256>>>(ei);
    k_gemm1<<<(NN + G1_ROWS - 1) / G1_ROWS, G1_THREADS, SM1_TOTAL>>>(x, W1);  // 4th -> profiled
    k_starts<<<NB, 256>>>();
    k_fill<<<(NE + 255) / 256, 256>>>(ei);
    k_gather1<<<(NN + 7) / 8, 256>>>(b1);
    k_gemm2<<<(NN + 255) / 256, 256>>>(W2);
    {
        long long threads = (long long)NN * 16;
        k_gather2<<<(unsigned)((threads + 255) / 256), 256>>>(b2, out);
    }
}